// round 16
// baseline (speedup 1.0000x reference)
#include <cuda_runtime.h>
#include <cstdint>

// SKA: out[n, g*8+c, h, w] = sum_{7x7} x_pad[n, g*8+c, h+i, w+j] * w[n, c, i*7+j, h, w]
// x [8,512,96,96] f32, w [8,8,49,96,96] f32, out [8,512,96,96] f32.
//
// R16: WARP-DECOUPLED pipelines. Evidence: issue stuck ~43% across R13-R15
// while no pipe >65% -- all 12 warps share one barrier, convoy into l1tex
// together, and stall together. Now each of the 6 warps owns a 4-row x 16-col
// output patch with a PRIVATE smem ring (4 buffers x 240 floats) and its own
// cp.async group pipeline; the ONLY sync is __syncwarp. No __syncthreads
// anywhere in the main loop; warps self-pace and desynchronize.
// Inside each warp: the proven R9 lane-pair quad (roles A/B share a 2x2 quad,
// A reads window rows 0..3, B rows 7..4; 49 weight pairs = 98 regs/lane;
// scalar odd taps; shfl.bfly(1) merge). R13 tail-split schedule kept:
// 1480 full-64ch CTAs (5 x 296 slots) + 56 tail tiles split 4-way.
// Staging is fully affine: smem offset of element k is (lane+32k)*4; every
// smem float is rewritten each stage (ZFILL for halo/OOB) -> no zero-init.

#define N_    8
#define IC    512
#define H_    96
#define W_    96
#define WC    8
#define G_    64
#define PAD   3
#define HT    4                     // output rows per CTA tile
#define NTHR  192                   // 6 warps x 32
#define WP_COLS 16                  // output cols per warp
#define TROWS 10                    // staged rows per warp window
#define TPITCH 24                   // 22 data cols + 2 pad
#define TILE_F (TROWS * TPITCH)     // 240 floats per channel buffer
#define NBUF  4                     // ring depth per warp
#define HW    (H_ * W_)             // 9216
#define CSTR  ((size_t)WC * HW)     // x/out channel stride between g steps

#define NTILE 1536                  // 24 ht x 8 c x 8 n
#define FULLT 1480                  // full-64g tiles (= 5 * 296 slots exactly)
#define SPLITK 4                    // tail tiles split into 4 CTAs x 16 g
#define GRIDX (FULLT + (NTILE - FULLT) * SPLITK)   // 1480 + 224 = 1704

typedef unsigned long long u64;

static __device__ __forceinline__ void ffma2(u64& d, u64 a, u64 b) {
    asm("fma.rn.f32x2 %0, %1, %2, %0;" : "+l"(d) : "l"(a), "l"(b));
}
static __device__ __forceinline__ u64 fadd2(u64 a, u64 b) {
    u64 d; asm("add.rn.f32x2 %0, %1, %2;" : "=l"(d) : "l"(a), "l"(b)); return d;
}
// lo += xl*w.lo, hi += xh*w.hi; splitting the weight pair is register aliasing.
static __device__ __forceinline__ void odd_tap(float& lo, float& hi,
                                               float xl, float xh, u64 w) {
    asm("{\n\t"
        ".reg .f32 wl, wh;\n\t"
        "mov.b64 {wl, wh}, %4;\n\t"
        "fma.rn.f32 %0, %2, wl, %0;\n\t"
        "fma.rn.f32 %1, %3, wh, %1;\n\t"
        "}" : "+f"(lo), "+f"(hi) : "f"(xl), "f"(xh), "l"(w));
}
static __device__ __forceinline__ void unpack2(u64 v, float& a, float& b) {
    asm("mov.b64 {%0, %1}, %2;" : "=f"(a), "=f"(b) : "l"(v));
}
static __device__ __forceinline__ u64 pack2(float a, float b) {
    u64 r; asm("mov.b64 %0, {%1, %2};" : "=l"(r) : "f"(a), "f"(b)); return r;
}
static __device__ __forceinline__ u64 shfl_x1(u64 v) {
    uint32_t lo = (uint32_t)v, hi = (uint32_t)(v >> 32);
    lo = __shfl_xor_sync(0xffffffffu, lo, 1);
    hi = __shfl_xor_sync(0xffffffffu, hi, 1);
    return ((u64)hi << 32) | lo;
}
// cp.async ZFILL idiom: sz==0 reads nothing (src address unused), writes zeros.
static __device__ __forceinline__ void cp4(uint32_t s, const float* g, int sz) {
    asm volatile("cp.async.ca.shared.global [%0], [%1], 4, %2;"
                 :: "r"(s), "l"(g), "r"(sz));
}

// 7 taps of one kernel row into one chain set (even pairs + odd scalars).
#define TAP7(E, LO, HI, WA)                          \
    do {                                             \
        ffma2(E, U0, (WA)[0]);                       \
        ffma2(E, U1, (WA)[2]);                       \
        ffma2(E, U2, (WA)[4]);                       \
        ffma2(E, U3, (WA)[6]);                       \
        odd_tap(LO, HI, f1, f2, (WA)[1]);            \
        odd_tap(LO, HI, f3, f4, (WA)[3]);            \
        odd_tap(LO, HI, f5, f6, (WA)[5]);            \
    } while (0)

#define LOADROW(ptr)                                 \
    const u64* rp = (const u64*)(ptr);               \
    u64 U0 = rp[0], U1 = rp[1], U2 = rp[2], U3 = rp[3];  \
    float f0, f1, f2, f3, f4, f5, f6, f7;            \
    unpack2(U0, f0, f1); unpack2(U1, f2, f3);        \
    unpack2(U2, f4, f5); unpack2(U3, f6, f7)

__global__ __launch_bounds__(NTHR, 2)
void ska_kernel(const float* __restrict__ x, const float* __restrict__ wgt,
                float* __restrict__ out) {
    // Per-warp private rings: [warp][buf][240 floats] = 23 KB total.
    __shared__ float smem[6 * NBUF * TILE_F];

    const int tid  = threadIdx.x;
    const int warp = tid >> 5;           // 0..5 -> col block 16*warp
    const int lane = tid & 31;
    // ---- Tail-split schedule decode (uniform across the CTA) ----
    int tile, g0, ng;
    {
        int bid = blockIdx.x;
        if (bid < FULLT) { tile = bid;                 g0 = 0;  ng = G_; }
        else {
            int r = bid - FULLT;                       // 0..223
            tile = FULLT + (r >> 2);                   // 4 consecutive bids/tile
            g0   = (r & 3) * (G_ / SPLITK);            // 0,16,32,48
            ng   = G_ / SPLITK;                        // 16
        }
    }
    const int ht   = tile % 24;
    const int c    = (tile / 24) % WC;
    const int n    = tile / (24 * WC);
    const int h0   = ht * HT;
    const int cs   = warp;               // col block: output cols 16cs..16cs+15
    const int role = lane & 1;           // 0 = A (win rows 0..3), 1 = B (7..4)
    const int pid  = lane >> 1;          // 0..15
    const int rgL  = pid >> 3;           // row-group within warp: rows 2rgL,+1
    const int cp   = pid & 7;            // col-pair within warp
    const int w0g  = WP_COLS * cs + 2 * cp;   // global output col of pair

    // ---- Affine staging descriptors (per lane, 8 elements per channel) ----
    // Element k lives at smem float index (lane + 32k) within the buffer:
    // row = idx/24, col = idx%24. Data: smem col cc holds x col 16cs+cc-3,
    // smem row r holds x row h0-3+r. Invalid (pad cols 22..23, OOB rows/cols)
    // -> ZFILL. k=7 covers idx 224..255; lanes >=16 there are out-of-tile and
    // must SKIP (not ZFILL) to avoid writing past the buffer.
    const float* xc = x + (size_t)n * IC * HW + (size_t)c * HW
                        + (size_t)g0 * CSTR;     // first channel of this CTA
    int gofs[8];
    unsigned vmask = 0;
    #pragma unroll
    for (int k = 0; k < 8; k++) {
        int idx = lane + 32 * k;
        int row = idx / TPITCH, col = idx % TPITCH;
        int xr  = h0 - PAD + row;
        int xcl = WP_COLS * cs + col - PAD;
        bool v  = (idx < TILE_F) && (col <= 21) &&
                  (xr >= 0) && (xr < H_) && (xcl >= 0) && (xcl < W_);
        if (v) vmask |= 1u << k;
        int xrc = xr  < 0 ? 0 : (xr  > H_ - 1 ? H_ - 1 : xr);
        int xcc = xcl < 0 ? 0 : (xcl > W_ - 1 ? W_ - 1 : xcl);
        gofs[k] = xrc * W_ + xcc;        // clamped (safe) address; mask gates
    }
    const uint32_t sbaseW = (uint32_t)__cvta_generic_to_shared(smem)
                          + (uint32_t)(warp * NBUF * TILE_F) * 4u
                          + (uint32_t)lane * 4u;
    // Stage channel s into ring slot s&3; one cp.async commit group per call.
    auto stage = [&](int s) {
        uint32_t sb = sbaseW + (uint32_t)((s & 3) * TILE_F) * 4u;
        const float* base = xc + (size_t)s * CSTR;
        #pragma unroll
        for (int k = 0; k < 7; k++)
            cp4(sb + (uint32_t)(k * 128), base + gofs[k],
                (int)(((vmask >> k) & 1u) << 2));
        if (lane < 16)                   // k=7: only idx 224..239 are in-tile
            cp4(sb + (uint32_t)(7 * 128), base + gofs[7],
                (int)(((vmask >> 7) & 1u) << 2));
        asm volatile("cp.async.commit_group;");
    };

    // Fill the pipeline first so the scattered weight LDGs overlap it.
    stage(0);
    stage(1);
    stage(2);

    // ---- Weight register cache: exactly 49 pairs per lane (98 regs) ----
    // own = pixel this role stores (A: row h0+2rgL; B: +1).
    // A: light = own i=0;  heavy m=0..2: own i=m+1, other i=m.
    // B: light = own i=6;  heavy m=0..2: own i=5-m, other i=6-m.
    const float* W0b = wgt + ((size_t)(n * WC + c) * 49) * HW
                           + (size_t)(h0 + 2 * rgL) * W_ + w0g;
    const float* ownB = role ? (W0b + W_) : W0b;
    const float* othB = role ? W0b : (W0b + W_);
    u64 WL[7], WHo[3][7], WHx[3][7];
    {
        const int liRow = role ? 6 : 0;
        #pragma unroll
        for (int j = 0; j < 7; j++)
            WL[j] = *(const u64*)(ownB + (size_t)(liRow * 7 + j) * HW);
        #pragma unroll
        for (int m = 0; m < 3; m++) {
            const int ro = role ? (5 - m) : (m + 1);
            const int rx = role ? (6 - m) : m;
            #pragma unroll
            for (int j = 0; j < 7; j++) {
                WHo[m][j] = *(const u64*)(ownB + (size_t)(ro * 7 + j) * HW);
                WHx[m][j] = *(const u64*)(othB + (size_t)(rx * 7 + j) * HW);
            }
        }
    }

    // Per-lane window-row float offsets: A reads window row kk, B row 7-kk.
    // Window row r (of this quad) = tile row 2rgL + r; pair cols start at
    // smem col 2cp (= x col 16cs+2cp-3, the j=0 tap). 8B aligned (even*4B).
    int rowF[4];
    #pragma unroll
    for (int kk = 0; kk < 4; kk++)
        rowF[kk] = (2 * rgL + (role ? (7 - kk) : kk)) * TPITCH + 2 * cp;

    float* op = out + (size_t)n * IC * HW + (size_t)c * HW
                    + (size_t)g0 * CSTR
                    + (size_t)(h0 + 2 * rgL + role) * W_ + w0g;
    const float* tbW = smem + warp * NBUF * TILE_F;

    for (int g = 0; g < ng; ++g) {
        // Ensure group g landed (pending = staged_max - g <= 2 normally).
        if (g + 2 < ng)      { asm volatile("cp.async.wait_group 2;"); }
        else if (g + 1 < ng) { asm volatile("cp.async.wait_group 1;"); }
        else                 { asm volatile("cp.async.wait_group 0;"); }
        __syncwarp();
        // All lanes are past compute(g-1) (it precedes this syncwarp in each
        // lane's program order), so ring slot (g+3)&3 = (g-1)&3 is reusable.
        if (g + 3 < ng) stage(g + 3);

        const float* tb = tbW + (g & 3) * TILE_F;
        u64 eO = 0ull, eX = 0ull;               // even-tap chains
        float oLo = 0.f, oHi = 0.f, xLo = 0.f, xHi = 0.f;  // odd scalars
        {   // light row (kk=0): 7 taps, own pixel only
            LOADROW(tb + rowF[0]);
            TAP7(eO, oLo, oHi, WL);
        }
        #pragma unroll
        for (int kk = 1; kk < 4; kk++) {        // heavy rows: own + other
            LOADROW(tb + rowF[kk]);
            TAP7(eO, oLo, oHi, WHo[kk - 1]);
            TAP7(eX, xLo, xHi, WHx[kk - 1]);
        }
        u64 ownF = fadd2(eO, pack2(oLo, oHi));
        u64 othF = fadd2(eX, pack2(xLo, xHi));
        u64 recv = shfl_x1(othF);               // partner's partial, MY pixel
        *(u64*)op = fadd2(ownF, recv);
        op += CSTR;
    }
}

extern "C" void kernel_launch(void* const* d_in, const int* in_sizes, int n_in,
                              void* d_out, int out_size) {
    const float* x = (const float*)d_in[0];
    const float* w = (const float*)d_in[1];
    // x (37,748,736 elems) > w (28,901,376); guard against input ordering.
    if (n_in >= 2 && in_sizes[0] < in_sizes[1]) {
        const float* t = x; x = w; w = t;
    }
    float* out = (float*)d_out;
    ska_kernel<<<GRIDX, NTHR>>>(x, w, out);   // 1480 full + 224 tail CTAs
}

// round 17
// speedup vs baseline: 1.4599x; 1.4599x over previous
#include <cuda_runtime.h>
#include <cstdint>

// SKA: out[n, g*8+c, h, w] = sum_{7x7} x_pad[n, g*8+c, h+i, w+j] * w[n, c, i*7+j, h, w]
// x [8,512,96,96] f32, w [8,8,49,96,96] f32, out [8,512,96,96] f32.
//
// R17: 4 INDEPENDENT CTAs per SM (96 threads each), conflict-free layout kept.
// R16's warp-private rings died of bank conflicts (TPITCH=24 broke the
// PITCH%32==16 invariant that keeps role-A/role-B rows on disjoint 16-bank
// halves) -- the decoupling idea itself was never tested. This round tests it
// cleanly: CTA = 2 output rows x 96 cols = one lane-pair-quad row-group
// (3 warps), PITCH=112 exactly as in the proven R9-R14 body, 4 CTAs/SM
// (4 barrier domains, 4 cp.async pipelines; a __syncthreads stalls 3 warps,
// not 6). 49 weight pairs = 98 regs/lane unchanged. Staging is fully affine:
// col = tid (96 threads == W), rows 0..7, one 8-bit validity mask.
// Tail-split rebuilt for 592 slots: 2960 full tiles = exactly 5 waves, the
// last 112 tiles split 4-way (448 quarter CTAs = one short backfill wave).

#define N_    8
#define IC    512
#define H_    96
#define W_    96
#define WC    8
#define G_    64
#define PAD   3
#define HT    2                     // output rows per CTA (one quad row-group)
#define NTHR  96                    // 3 warps; == W_ (affine staging)
#define TROWS (HT + 2 * PAD)        // 8 staged rows
#define PITCH 112                   // 3 zero | 96 data | zeros; 112%32==16
#define TILE_F (TROWS * PITCH)      // 896 floats per channel slab
#define HW    (H_ * W_)             // 9216
#define CSTR  ((size_t)WC * HW)     // x/out channel stride between g steps
#define CPB   4                     // channels per pipeline block

#define NTILE 3072                  // 48 ht x 8 c x 8 n
#define FULLT 2960                  // full-64g tiles (= 5 * 592 slots exactly)
#define SPLITK 4                    // tail tiles split into 4 CTAs x 16 g
#define GRIDX (FULLT + (NTILE - FULLT) * SPLITK)   // 2960 + 448 = 3408

typedef unsigned long long u64;

static __device__ __forceinline__ void ffma2(u64& d, u64 a, u64 b) {
    asm("fma.rn.f32x2 %0, %1, %2, %0;" : "+l"(d) : "l"(a), "l"(b));
}
static __device__ __forceinline__ u64 fadd2(u64 a, u64 b) {
    u64 d; asm("add.rn.f32x2 %0, %1, %2;" : "=l"(d) : "l"(a), "l"(b)); return d;
}
// lo += xl*w.lo, hi += xh*w.hi; splitting the weight pair is register aliasing.
static __device__ __forceinline__ void odd_tap(float& lo, float& hi,
                                               float xl, float xh, u64 w) {
    asm("{\n\t"
        ".reg .f32 wl, wh;\n\t"
        "mov.b64 {wl, wh}, %4;\n\t"
        "fma.rn.f32 %0, %2, wl, %0;\n\t"
        "fma.rn.f32 %1, %3, wh, %1;\n\t"
        "}" : "+f"(lo), "+f"(hi) : "f"(xl), "f"(xh), "l"(w));
}
static __device__ __forceinline__ void unpack2(u64 v, float& a, float& b) {
    asm("mov.b64 {%0, %1}, %2;" : "=f"(a), "=f"(b) : "l"(v));
}
static __device__ __forceinline__ u64 pack2(float a, float b) {
    u64 r; asm("mov.b64 %0, {%1, %2};" : "=l"(r) : "f"(a), "f"(b)); return r;
}
static __device__ __forceinline__ u64 shfl_x1(u64 v) {
    uint32_t lo = (uint32_t)v, hi = (uint32_t)(v >> 32);
    lo = __shfl_xor_sync(0xffffffffu, lo, 1);
    hi = __shfl_xor_sync(0xffffffffu, hi, 1);
    return ((u64)hi << 32) | lo;
}
static __device__ __forceinline__ void cp4(uint32_t s, const float* g, int sz) {
    asm volatile("cp.async.ca.shared.global [%0], [%1], 4, %2;"
                 :: "r"(s), "l"(g), "r"(sz));
}

// 7 taps of one kernel row into one chain set (even pairs + odd scalars).
#define TAP7(E, LO, HI, WA)                          \
    do {                                             \
        ffma2(E, U0, (WA)[0]);                       \
        ffma2(E, U1, (WA)[2]);                       \
        ffma2(E, U2, (WA)[4]);                       \
        ffma2(E, U3, (WA)[6]);                       \
        odd_tap(LO, HI, f1, f2, (WA)[1]);            \
        odd_tap(LO, HI, f3, f4, (WA)[3]);            \
        odd_tap(LO, HI, f5, f6, (WA)[5]);            \
    } while (0)

#define LOADROW(ptr)                                 \
    const u64* rp = (const u64*)(ptr);               \
    u64 U0 = rp[0], U1 = rp[1], U2 = rp[2], U3 = rp[3];  \
    float f0, f1, f2, f3, f4, f5, f6, f7;            \
    unpack2(U0, f0, f1); unpack2(U1, f2, f3);        \
    unpack2(U2, f4, f5); unpack2(U3, f6, f7)

__global__ __launch_bounds__(NTHR, 4)
void ska_kernel(const float* __restrict__ x, const float* __restrict__ wgt,
                float* __restrict__ out) {
    __shared__ float smem[8 * TILE_F];   // 2 buffers x 4 channel slabs = 28.7 KB

    const int tid  = threadIdx.x;
    // ---- Tail-split schedule decode (uniform across the CTA) ----
    int tile, g0, nblk;
    {
        int bid = blockIdx.x;
        if (bid < FULLT) { tile = bid;                 g0 = 0;  nblk = G_ / CPB; }
        else {
            int r = bid - FULLT;                       // 0..447
            tile = FULLT + (r >> 2);                   // 4 consecutive bids/tile
            g0   = (r & 3) * (G_ / SPLITK);            // 0,16,32,48
            nblk = (G_ / SPLITK) / CPB;                // 4
        }
    }
    const int ht   = tile % 48;
    const int c    = (tile / 48) % WC;
    const int n    = tile / (48 * WC);
    const int h0   = ht * HT;
    const int role = tid & 1;            // 0 = A (win rows 0..3), 1 = B (7..4)
    const int pid  = tid >> 1;           // 0..47 = col pair
    const int w0   = 2 * pid;

    // Zero left/right halo columns of all 8 slabs (reads touch floats 0..101).
    for (int z = tid; z < 8 * TROWS * 8; z += NTHR) {
        int b = z / (TROWS * 8), rem = z % (TROWS * 8);
        int row = rem / 8, ci = rem % 8;
        int col = (ci < 3) ? ci : 99 + (ci - 3);
        smem[b * TILE_F + row * PITCH + col] = 0.0f;
    }

    // Affine staging: thread stages column tid of rows 0..7 (8 cp4/channel).
    const float* xc = x + (size_t)n * IC * HW + (size_t)c * HW
                        + (size_t)g0 * CSTR;     // first channel of this CTA
    const uint32_t sbase = (uint32_t)__cvta_generic_to_shared(smem)
                         + (uint32_t)(3 + tid) * 4u;
    int      gofs[TROWS];  // float offset within a channel (row-clamped)
    unsigned vmask = 0;    // bit k: row k in-bounds (copy 4B) else ZFILL
    #pragma unroll
    for (int k = 0; k < TROWS; k++) {
        int hr = h0 - PAD + k;
        if (hr >= 0 && hr < H_) vmask |= 1u << k;
        int hrc = hr < 0 ? 0 : (hr >= H_ ? H_ - 1 : hr);
        gofs[k] = hrc * W_ + tid;
    }
    // Stage block b = local channels 4b..4b+3 into buffer b&1; one commit group.
    auto stage = [&](int b) {
        #pragma unroll
        for (int cc = 0; cc < CPB; cc++) {
            uint32_t sb = sbase + (uint32_t)(((b & 1) * CPB + cc) * TILE_F) * 4u;
            const float* base = xc + (size_t)(CPB * b + cc) * CSTR;
            #pragma unroll
            for (int k = 0; k < TROWS; k++)
                cp4(sb + (uint32_t)(k * PITCH * 4), base + gofs[k],
                    (int)(((vmask >> k) & 1u) << 2));
        }
        asm volatile("cp.async.commit_group;");
    };

    // Kick off both x buffers BEFORE the weight fill so the ~98 scattered
    // weight LDGs below overlap the x pipeline fill.
    stage(0);
    stage(1);

    // Weight register cache: exactly 49 pairs per thread (98 regs).
    // own = pixel this role stores (A: row h0; B: row h0+1).
    // A: light = own i=0;  heavy m=0..2: own i=m+1, other i=m.
    // B: light = own i=6;  heavy m=0..2: own i=5-m, other i=6-m.
    const float* W0b = wgt + ((size_t)(n * WC + c) * 49) * HW
                           + (size_t)h0 * W_ + w0;
    const float* ownB = role ? (W0b + W_) : W0b;
    const float* othB = role ? W0b : (W0b + W_);
    u64 WL[7], WHo[3][7], WHx[3][7];
    {
        const int liRow = role ? 6 : 0;
        #pragma unroll
        for (int j = 0; j < 7; j++)
            WL[j] = *(const u64*)(ownB + (size_t)(liRow * 7 + j) * HW);
        #pragma unroll
        for (int m = 0; m < 3; m++) {
            const int ro = role ? (5 - m) : (m + 1);
            const int rx = role ? (6 - m) : m;
            #pragma unroll
            for (int j = 0; j < 7; j++) {
                WHo[m][j] = *(const u64*)(ownB + (size_t)(ro * 7 + j) * HW);
                WHx[m][j] = *(const u64*)(othB + (size_t)(rx * 7 + j) * HW);
            }
        }
    }

    // Per-thread window-row float offsets: A reads row kk, B row 7-kk.
    int rowF[4];
    #pragma unroll
    for (int kk = 0; kk < 4; kk++)
        rowF[kk] = (role ? (7 - kk) : kk) * PITCH + w0;

    float* op = out + (size_t)n * IC * HW + (size_t)c * HW
                    + (size_t)g0 * CSTR
                    + (size_t)(h0 + role) * W_ + w0;

    for (int b = 0; b < nblk; ++b) {
        // b=0: groups {0,1} committed, need group 0 -> wait_group 1.
        // b>=1: drain all (group b), then stage b+1 into buffer (b+1)&1 =
        // (b-1)&1 -- safe, the barrier proved compute b-1 finished. The first
        // barrier also publishes the halo zeros written above.
        if (b == 0) { asm volatile("cp.async.wait_group 1;"); }
        else        { asm volatile("cp.async.wait_group 0;"); }
        __syncthreads();
        if (b >= 1 && b + 1 < nblk) stage(b + 1);

        const float* bufB = smem + (b & 1) * CPB * TILE_F;
        #pragma unroll
        for (int gg = 0; gg < CPB; gg++) {
            const float* tb = bufB + gg * TILE_F;
            u64 eO = 0ull, eX = 0ull;               // even-tap chains
            float oLo = 0.f, oHi = 0.f, xLo = 0.f, xHi = 0.f;  // odd scalars
            {   // light row (kk=0): 7 taps, own pixel only
                LOADROW(tb + rowF[0]);
                TAP7(eO, oLo, oHi, WL);
            }
            #pragma unroll
            for (int kk = 1; kk < 4; kk++) {        // heavy rows: own + other
                LOADROW(tb + rowF[kk]);
                TAP7(eO, oLo, oHi, WHo[kk - 1]);
                TAP7(eX, xLo, xHi, WHx[kk - 1]);
            }
            u64 ownF = fadd2(eO, pack2(oLo, oHi));
            u64 othF = fadd2(eX, pack2(xLo, xHi));
            u64 recv = shfl_x1(othF);               // partner's partial, MY px
            *(u64*)op = fadd2(ownF, recv);
            op += CSTR;
        }
    }
}

extern "C" void kernel_launch(void* const* d_in, const int* in_sizes, int n_in,
                              void* d_out, int out_size) {
    const float* x = (const float*)d_in[0];
    const float* w = (const float*)d_in[1];
    // x (37,748,736 elems) > w (28,901,376); guard against input ordering.
    if (n_in >= 2 && in_sizes[0] < in_sizes[1]) {
        const float* t = x; x = w; w = t;
    }
    float* out = (float*)d_out;
    ska_kernel<<<GRIDX, NTHR>>>(x, w, out);   // 2960 full + 448 tail CTAs
}